// round 4
// baseline (speedup 1.0000x reference)
#include <cuda_runtime.h>
#include <math.h>

#define NN 50000
#define NE 800000
#define FD 256
#define HEADS 4
#define CH 64

// ---- scratch (static device globals: no runtime allocation) ----
__device__ float g_h[(size_t)NN * FD];     // GEMM output of current layer
__device__ float g_y[(size_t)NN * FD];     // layer-1 output (GEMM input of layer 2)
__device__ float g_asrc[NN * HEADS];
__device__ float g_adst[NN * HEADS];
__device__ float g_wt[(size_t)NE * HEADS]; // per-(edge,head) unnormalized softmax wt
__device__ int   g_cnt[NN];
__device__ int   g_off[NN + 1];
__device__ int   g_col[NE];                // CSR: src per position
__device__ int   g_row[NE];                // CSR: dst per position

__device__ __forceinline__ float lrelu(float x) { return fmaxf(x, 0.2f * x); }

__device__ __forceinline__ unsigned f2tf(float f) {
    unsigned u;
    asm("cvt.rna.tf32.f32 %0, %1;" : "=r"(u) : "f"(f));
    return u;
}

__device__ __forceinline__ void mma_tf32(float* c, const unsigned* a, const unsigned* b) {
    asm volatile(
        "mma.sync.aligned.m16n8k8.row.col.f32.tf32.tf32.f32 "
        "{%0,%1,%2,%3},{%4,%5,%6,%7},{%8,%9},{%0,%1,%2,%3};"
        : "+f"(c[0]), "+f"(c[1]), "+f"(c[2]), "+f"(c[3])
        : "r"(a[0]), "r"(a[1]), "r"(a[2]), "r"(a[3]), "r"(b[0]), "r"(b[1]));
}

// ---------------- CSR build ----------------
__global__ void k_zero_cnt() {
    int i = blockIdx.x * blockDim.x + threadIdx.x;
    if (i < NN) g_cnt[i] = 0;
}

__global__ void k_hist(const int* __restrict__ dst) {
    int e = blockIdx.x * blockDim.x + threadIdx.x;
    if (e < NE) atomicAdd(&g_cnt[dst[e]], 1);
}

// single-block shuffle scan: 1024 threads x 49 contiguous counts each.
// Writes exclusive prefix to g_off, re-zeros g_cnt, sets g_off[NN]=total.
__global__ void k_scan() {
    const int T = 1024, PER = (NN + T - 1) / T;   // 49
    __shared__ int wsum[32];
    const int t = threadIdx.x, lane = t & 31, wid = t >> 5;
    const int base = t * PER;

    int sum = 0;
    for (int i = 0; i < PER; i++) {
        int idx = base + i;
        if (idx < NN) sum += g_cnt[idx];
    }
    int v = sum;
#pragma unroll
    for (int o = 1; o < 32; o <<= 1) {
        int n = __shfl_up_sync(0xffffffffu, v, o);
        if (lane >= o) v += n;
    }
    if (lane == 31) wsum[wid] = v;
    __syncthreads();
    if (wid == 0) {
        int wv = wsum[lane];
#pragma unroll
        for (int o = 1; o < 32; o <<= 1) {
            int n = __shfl_up_sync(0xffffffffu, wv, o);
            if (lane >= o) wv += n;
        }
        wsum[lane] = wv;
    }
    __syncthreads();
    int run = v - sum + (wid > 0 ? wsum[wid - 1] : 0);   // exclusive prefix
    for (int i = 0; i < PER; i++) {
        int idx = base + i;
        if (idx < NN) {
            int c = g_cnt[idx];
            g_off[idx] = run;
            run += c;
            g_cnt[idx] = 0;
        }
    }
    if (t == 0) g_off[NN] = wsum[31];
}

__global__ void k_scatter(const int* __restrict__ src, const int* __restrict__ dst) {
    int e = blockIdx.x * blockDim.x + threadIdx.x;
    if (e < NE) {
        int d = dst[e];
        int pos = g_off[d] + atomicAdd(&g_cnt[d], 1);
        g_col[pos] = src[e];
        g_row[pos] = d;
    }
}

// ---------------- tf32 tensor-core GEMM + fused attention-logit epilogue ----
// Block tile 64(M) x 256(N=all heads), BK=16, 256 threads = 8 warps (4 wm x 2 wn).
// Register-prefetch double buffering; conflict-free LDS (A stride 20, B 264).
__global__ void __launch_bounds__(256) k_gemm_att(
    const float* __restrict__ Ain,          // nullptr -> use g_y
    const float* __restrict__ W,
    const float* __restrict__ att_s,
    const float* __restrict__ att_d)
{
    const float* A = Ain ? Ain : g_y;
    __shared__ unsigned sA[64][20];
    __shared__ unsigned sB[16][264];

    const int t    = threadIdx.x;
    const int lane = t & 31;
    const int wid  = t >> 5;
    const int gid  = lane >> 2, tig = lane & 3;
    const int wm   = wid & 3,   wn  = wid >> 2;
    const int row0 = blockIdx.x * 64;

    float acc[16][4] = {};

    const int ar = t >> 2, ac = (t & 3) * 4;
    const int br = t >> 4, bc = (t & 15) * 4;
    const bool arow_ok = (row0 + ar) < NN;
    const float* aptr = A + (size_t)(row0 + ar) * FD + ac;
    const float* bptr = W + (size_t)br * FD + bc;

    float4 aval = make_float4(0.f, 0.f, 0.f, 0.f);
    float4 bval[4];
    if (arow_ok) aval = *(const float4*)aptr;
#pragma unroll
    for (int sub = 0; sub < 4; sub++)
        bval[sub] = *(const float4*)(bptr + sub * 64);

    for (int k0 = 0; k0 < FD; k0 += 16) {
        *(uint4*)&sA[ar][ac] = make_uint4(f2tf(aval.x), f2tf(aval.y),
                                          f2tf(aval.z), f2tf(aval.w));
#pragma unroll
        for (int sub = 0; sub < 4; sub++)
            *(uint4*)&sB[br][bc + sub * 64] =
                make_uint4(f2tf(bval[sub].x), f2tf(bval[sub].y),
                           f2tf(bval[sub].z), f2tf(bval[sub].w));
        __syncthreads();

        if (k0 + 16 < FD) {
            aval = make_float4(0.f, 0.f, 0.f, 0.f);
            if (arow_ok) aval = *(const float4*)(aptr + k0 + 16);
#pragma unroll
            for (int sub = 0; sub < 4; sub++)
                bval[sub] = *(const float4*)(bptr + (size_t)(k0 + 16) * FD + sub * 64);
        }

#pragma unroll
        for (int kk = 0; kk < 16; kk += 8) {
            unsigned af[4];
            const int r = wm * 16 + gid;
            af[0] = sA[r    ][kk + tig];
            af[1] = sA[r + 8][kk + tig];
            af[2] = sA[r    ][kk + tig + 4];
            af[3] = sA[r + 8][kk + tig + 4];
            unsigned bf[16][2];
#pragma unroll
            for (int tn = 0; tn < 16; tn++) {
                const int c = wn * 128 + tn * 8 + gid;
                bf[tn][0] = sB[kk + tig    ][c];
                bf[tn][1] = sB[kk + tig + 4][c];
            }
#pragma unroll
            for (int tn = 0; tn < 16; tn++)
                mma_tf32(acc[tn], af, bf[tn]);
        }
        __syncthreads();
    }

    // ---- epilogue: store h, fused per-head attention dots ----
#pragma unroll
    for (int rh = 0; rh < 2; rh++) {
        const int r = row0 + wm * 16 + rh * 8 + gid;
        const bool rok = r < NN;
        if (rok) {
#pragma unroll
            for (int tn = 0; tn < 16; tn++) {
                const int c = wn * 128 + tn * 8 + 2 * tig;
                *(float2*)(g_h + (size_t)r * FD + c) =
                    make_float2(acc[tn][rh * 2], acc[tn][rh * 2 + 1]);
            }
        }
#pragma unroll
        for (int h2 = 0; h2 < 2; h2++) {
            float s_ = 0.f, d_ = 0.f;
#pragma unroll
            for (int tn8 = 0; tn8 < 8; tn8++) {
                const int tn = h2 * 8 + tn8;
                const int c = wn * 128 + tn * 8 + 2 * tig;
                const float v0 = acc[tn][rh * 2], v1 = acc[tn][rh * 2 + 1];
                s_ = fmaf(v0, att_s[c], fmaf(v1, att_s[c + 1], s_));
                d_ = fmaf(v0, att_d[c], fmaf(v1, att_d[c + 1], d_));
            }
            s_ += __shfl_xor_sync(0xffffffffu, s_, 1);
            s_ += __shfl_xor_sync(0xffffffffu, s_, 2);
            d_ += __shfl_xor_sync(0xffffffffu, d_, 1);
            d_ += __shfl_xor_sync(0xffffffffu, d_, 2);
            if (tig == 0 && rok) {
                const int head = wn * 2 + h2;
                g_asrc[r * HEADS + head] = s_;
                g_adst[r * HEADS + head] = d_;
            }
        }
    }
}

// ---------------- edge-parallel softmax weights ----------------
// thread i -> (pos = i/4, head = i%4). All gathers hit small L2-resident
// tables; exp moved OUT of the latency-critical aggregation loop.
__global__ void __launch_bounds__(256) k_edge_wt() {
    int i = blockIdx.x * blockDim.x + threadIdx.x;
    if (i < NE * HEADS) {
        int pos = i >> 2, h = i & 3;
        int s = g_col[pos], d = g_row[pos];
        g_wt[i] = __expf(lrelu(g_asrc[s * HEADS + h] + g_adst[d * HEADS + h]));
    }
}

// ---------------- per-dst-node aggregation: one warp per node ----------------
// Pure weighted gather: per edge 1 coalesced wt load + 2 LDG.128 + 8 FMA.
// Unrolled x4 with batched loads -> 8+ h-row loads in flight (high MLP).
__global__ void __launch_bounds__(256) k_aggregate(
    const float* __restrict__ bias,
    float* __restrict__ outp)               // nullptr -> g_y
{
    const int w = (blockIdx.x * blockDim.x + threadIdx.x) >> 5;
    const int lane = threadIdx.x & 31;
    if (w >= NN) return;
    const int hd = lane >> 3;
    const int beg = g_off[w], end = g_off[w + 1];

    // self loop
    float wt0 = __expf(lrelu(g_asrc[w * HEADS + hd] + g_adst[w * HEADS + hd]));
    float denom = wt0;
    const float4* hp = (const float4*)(g_h + (size_t)w * FD + lane * 8);
    float4 v0 = hp[0], v1 = hp[1];
    float a0 = wt0 * v0.x, a1 = wt0 * v0.y, a2 = wt0 * v0.z, a3 = wt0 * v0.w;
    float a4 = wt0 * v1.x, a5 = wt0 * v1.y, a6 = wt0 * v1.z, a7 = wt0 * v1.w;

    int k = beg;
    for (; k + 4 <= end; k += 4) {
        const int s0 = g_col[k], s1 = g_col[k + 1], s2 = g_col[k + 2], s3 = g_col[k + 3];
        const float w0 = g_wt[(size_t)(k    ) * HEADS + hd];
        const float w1 = g_wt[(size_t)(k + 1) * HEADS + hd];
        const float w2 = g_wt[(size_t)(k + 2) * HEADS + hd];
        const float w3 = g_wt[(size_t)(k + 3) * HEADS + hd];
        const float4* p0 = (const float4*)(g_h + (size_t)s0 * FD + lane * 8);
        const float4* p1 = (const float4*)(g_h + (size_t)s1 * FD + lane * 8);
        const float4* p2 = (const float4*)(g_h + (size_t)s2 * FD + lane * 8);
        const float4* p3 = (const float4*)(g_h + (size_t)s3 * FD + lane * 8);
        const float4 x00 = p0[0], x01 = p0[1];
        const float4 x10 = p1[0], x11 = p1[1];
        const float4 x20 = p2[0], x21 = p2[1];
        const float4 x30 = p3[0], x31 = p3[1];
        denom += (w0 + w1) + (w2 + w3);
        a0 = fmaf(w0, x00.x, fmaf(w1, x10.x, fmaf(w2, x20.x, fmaf(w3, x30.x, a0))));
        a1 = fmaf(w0, x00.y, fmaf(w1, x10.y, fmaf(w2, x20.y, fmaf(w3, x30.y, a1))));
        a2 = fmaf(w0, x00.z, fmaf(w1, x10.z, fmaf(w2, x20.z, fmaf(w3, x30.z, a2))));
        a3 = fmaf(w0, x00.w, fmaf(w1, x10.w, fmaf(w2, x20.w, fmaf(w3, x30.w, a3))));
        a4 = fmaf(w0, x01.x, fmaf(w1, x11.x, fmaf(w2, x21.x, fmaf(w3, x31.x, a4))));
        a5 = fmaf(w0, x01.y, fmaf(w1, x11.y, fmaf(w2, x21.y, fmaf(w3, x31.y, a5))));
        a6 = fmaf(w0, x01.z, fmaf(w1, x11.z, fmaf(w2, x21.z, fmaf(w3, x31.z, a6))));
        a7 = fmaf(w0, x01.w, fmaf(w1, x11.w, fmaf(w2, x21.w, fmaf(w3, x31.w, a7))));
    }
    for (; k < end; k++) {
        const int s = g_col[k];
        const float wt = g_wt[(size_t)k * HEADS + hd];
        denom += wt;
        const float4* p = (const float4*)(g_h + (size_t)s * FD + lane * 8);
        const float4 x0 = p[0], x1 = p[1];
        a0 = fmaf(wt, x0.x, a0); a1 = fmaf(wt, x0.y, a1);
        a2 = fmaf(wt, x0.z, a2); a3 = fmaf(wt, x0.w, a3);
        a4 = fmaf(wt, x1.x, a4); a5 = fmaf(wt, x1.y, a5);
        a6 = fmaf(wt, x1.z, a6); a7 = fmaf(wt, x1.w, a7);
    }

    const float inv = 1.0f / (denom + 1e-16f);
    const float* bp = bias + lane * 8;
    float r0 = a0 * inv + bp[0], r1 = a1 * inv + bp[1];
    float r2 = a2 * inv + bp[2], r3 = a3 * inv + bp[3];
    float r4 = a4 * inv + bp[4], r5 = a5 * inv + bp[5];
    float r6 = a6 * inv + bp[6], r7 = a7 * inv + bp[7];
    r0 = r0 > 0.f ? r0 : expm1f(r0);  r1 = r1 > 0.f ? r1 : expm1f(r1);
    r2 = r2 > 0.f ? r2 : expm1f(r2);  r3 = r3 > 0.f ? r3 : expm1f(r3);
    r4 = r4 > 0.f ? r4 : expm1f(r4);  r5 = r5 > 0.f ? r5 : expm1f(r5);
    r6 = r6 > 0.f ? r6 : expm1f(r6);  r7 = r7 > 0.f ? r7 : expm1f(r7);

    float* op = (outp ? outp : g_y) + (size_t)w * FD + lane * 8;
    *(float4*)op       = make_float4(r0, r1, r2, r3);
    *((float4*)op + 1) = make_float4(r4, r5, r6, r7);
}

// ---------------- launch ----------------
extern "C" void kernel_launch(void* const* d_in, const int* in_sizes, int n_in,
                              void* d_out, int out_size)
{
    const float* x   = (const float*)d_in[0];
    const int*   ei  = (const int*)d_in[1];
    const float* W1  = (const float*)d_in[2];
    const float* as1 = (const float*)d_in[3];
    const float* ad1 = (const float*)d_in[4];
    const float* b1  = (const float*)d_in[5];
    const float* W2  = (const float*)d_in[6];
    const float* as2 = (const float*)d_in[7];
    const float* ad2 = (const float*)d_in[8];
    const float* b2  = (const float*)d_in[9];

    const int* src = ei;            // edge_index row 0
    const int* dst = ei + NE;       // edge_index row 1

    // CSR by dst (self loops handled implicitly in k_aggregate)
    k_zero_cnt<<<(NN + 255) / 256, 256>>>();
    k_hist<<<(NE + 255) / 256, 256>>>(dst);
    k_scan<<<1, 1024>>>();          // scan + re-zero g_cnt
    k_scatter<<<(NE + 255) / 256, 256>>>(src, dst);

    const int ggrid = (NN + 63) / 64;
    const int wgrid = (NE * HEADS + 255) / 256;
    const int agrid = (NN * 32 + 255) / 256;

    // layer 1
    k_gemm_att<<<ggrid, 256>>>(x, W1, as1, ad1);
    k_edge_wt<<<wgrid, 256>>>();
    k_aggregate<<<agrid, 256>>>(b1, nullptr);
    // layer 2
    k_gemm_att<<<ggrid, 256>>>(nullptr, W2, as2, ad2);
    k_edge_wt<<<wgrid, 256>>>();
    k_aggregate<<<agrid, 256>>>(b2, (float*)d_out);
}